// round 1
// baseline (speedup 1.0000x reference)
#include <cuda_runtime.h>
#include <cstdint>

#define L_SEQ 2048
#define BATCH 2
#define DMODEL 1024
#define NHEAD 16
#define DHEAD 64
#define DFF 3072
#define MTOT (BATCH * L_SEQ) /* 4096 */

// -------- scratch (device globals: allocation-free rule) --------
__device__ float g_xn[MTOT * DMODEL];        // 16 MB
__device__ float g_qkv[MTOT * 3 * DMODEL];   // 48 MB
__device__ float g_o[MTOT * DMODEL];         // 16 MB
__device__ float g_u[MTOT * 2 * DFF];        // 96 MB
__device__ float g_h[MTOT * DFF];            // 48 MB

// ---------------- RMSNorm: one block per row, 256 thr x float4 ----------------
__global__ void __launch_bounds__(256) rmsnorm_kernel(const float* __restrict__ x,
                                                      const float* __restrict__ scale,
                                                      float* __restrict__ out)
{
    int row = blockIdx.x;
    int t = threadIdx.x;
    const float4* xr = reinterpret_cast<const float4*>(x) + (size_t)row * (DMODEL / 4);
    float4 v = xr[t];
    float ss = v.x * v.x + v.y * v.y + v.z * v.z + v.w * v.w;
#pragma unroll
    for (int o = 16; o; o >>= 1) ss += __shfl_xor_sync(0xffffffffu, ss, o);
    __shared__ float ws[8];
    if ((t & 31) == 0) ws[t >> 5] = ss;
    __syncthreads();
    float tot = 0.f;
#pragma unroll
    for (int i = 0; i < 8; i++) tot += ws[i];
    float inv = rsqrtf(tot * (1.0f / DMODEL) + 1e-6f);
    float4 s = reinterpret_cast<const float4*>(scale)[t];
    float4 r;
    r.x = v.x * s.x * inv;
    r.y = v.y * s.y * inv;
    r.z = v.z * s.z * inv;
    r.w = v.w * s.w * inv;
    (reinterpret_cast<float4*>(out) + (size_t)row * (DMODEL / 4))[t] = r;
}

// ---------------- GEMM NT: C[m,n] = sum_k A[m,k]*B[n,k] (+resid) ----------------
// 128x128 tile, BK=8, 256 threads, 8x8 microtile (4+4 split for vectorized smem reads)
__global__ void __launch_bounds__(256) gemm_nt_kernel(const float* __restrict__ A,
                                                      const float* __restrict__ B,
                                                      const float* resid,
                                                      float* __restrict__ C,
                                                      int N, int K)
{
    __shared__ float As[8][132];
    __shared__ float Bs[8][132];
    int tid = threadIdx.x;
    int m0 = blockIdx.y * 128, n0 = blockIdx.x * 128;
    int lrow = tid >> 1;         // 0..127
    int lk = (tid & 1) * 4;      // 0 or 4
    const float* Ap = A + (size_t)(m0 + lrow) * K + lk;
    const float* Bp = B + (size_t)(n0 + lrow) * K + lk;
    int tx = tid & 15, ty = tid >> 4;

    float acc[8][8] = {};
    float4 av = *reinterpret_cast<const float4*>(Ap);
    float4 bv = *reinterpret_cast<const float4*>(Bp);

    for (int kt = 0; kt < K; kt += 8) {
        As[lk + 0][lrow] = av.x; As[lk + 1][lrow] = av.y;
        As[lk + 2][lrow] = av.z; As[lk + 3][lrow] = av.w;
        Bs[lk + 0][lrow] = bv.x; Bs[lk + 1][lrow] = bv.y;
        Bs[lk + 2][lrow] = bv.z; Bs[lk + 3][lrow] = bv.w;
        __syncthreads();
        if (kt + 8 < K) {  // prefetch next tile while computing
            av = *reinterpret_cast<const float4*>(Ap + kt + 8);
            bv = *reinterpret_cast<const float4*>(Bp + kt + 8);
        }
#pragma unroll
        for (int kk = 0; kk < 8; kk++) {
            float a[8], b[8];
#pragma unroll
            for (int i = 0; i < 4; i++) {
                a[i]     = As[kk][ty * 4 + i];
                a[i + 4] = As[kk][64 + ty * 4 + i];
                b[i]     = Bs[kk][tx * 4 + i];
                b[i + 4] = Bs[kk][64 + tx * 4 + i];
            }
#pragma unroll
            for (int i = 0; i < 8; i++)
#pragma unroll
                for (int j = 0; j < 8; j++)
                    acc[i][j] = fmaf(a[i], b[j], acc[i][j]);
        }
        __syncthreads();
    }

#pragma unroll
    for (int i = 0; i < 8; i++) {
        int m = m0 + (i < 4 ? ty * 4 + i : 64 + ty * 4 + i - 4);
#pragma unroll
        for (int j = 0; j < 8; j++) {
            int n = n0 + (j < 4 ? tx * 4 + j : 64 + tx * 4 + j - 4);
            float v = acc[i][j];
            if (resid) v += resid[(size_t)m * N + n];
            C[(size_t)m * N + n] = v;
        }
    }
}

// ---------------- QK cosine norm: one warp per (token, part, head) 64-vec ----------------
__global__ void __launch_bounds__(256) qknorm_kernel(float* __restrict__ qkv,
                                                     const float* __restrict__ attn_scale)
{
    int warp = blockIdx.x * (blockDim.x >> 5) + (threadIdx.x >> 5);
    int lane = threadIdx.x & 31;
    int m = warp >> 5;
    int rest = warp & 31;
    int part = rest >> 4;  // 0=q, 1=k
    int h = rest & 15;
    size_t base = (size_t)m * 3072 + part * 1024 + h * 64;
    float2 v = *reinterpret_cast<float2*>(qkv + base + lane * 2);
    float ss = v.x * v.x + v.y * v.y;
#pragma unroll
    for (int o = 16; o; o >>= 1) ss += __shfl_xor_sync(0xffffffffu, ss, o);
    float f = sqrtf(attn_scale[h]) * rsqrtf(ss + 1e-6f);
    v.x *= f;
    v.y *= f;
    *reinterpret_cast<float2*>(qkv + base + lane * 2) = v;
}

// ---------------- Flash attention: BM=64 queries, BN=32 keys per iter ----------------
// grid (L/64, NHEAD, BATCH), 256 threads (16x16), per-thread 4 rows x (2 score cols / 4 out dims)
__global__ void __launch_bounds__(256) attention_kernel(const float* __restrict__ qkv,
                                                        float* __restrict__ o)
{
    __shared__ float Qs[64][64];
    __shared__ float Ks[32][66];
    __shared__ float Vs[32][64];
    __shared__ float Ps[64][32];

    int tid = threadIdx.x;
    int tx = tid & 15, ty = tid >> 4;
    int q0 = blockIdx.x * 64;
    int h = blockIdx.y, b = blockIdx.z;
    const float* qbase = qkv + (size_t)b * L_SEQ * 3072 + h * 64;
    const float* kbase = qbase + 1024;
    const float* vbase = qbase + 2048;

    // load Q tile (64x64)
#pragma unroll
    for (int j = 0; j < 4; j++) {
        int idx = tid + 256 * j;
        int r = idx >> 4, seg = idx & 15;
        float4 v = *reinterpret_cast<const float4*>(qbase + (size_t)(q0 + r) * 3072 + seg * 4);
        *reinterpret_cast<float4*>(&Qs[r][seg * 4]) = v;
    }

    float acc[4][4] = {};
    float mrow[4], lrow[4];
#pragma unroll
    for (int a = 0; a < 4; a++) { mrow[a] = -1e30f; lrow[a] = 0.f; }

    for (int kb = 0; kb < L_SEQ / 32; kb++) {
        // load K (padded, scalar stores) and V tiles
#pragma unroll
        for (int j = 0; j < 2; j++) {
            int idx = tid + 256 * j;
            int r = idx >> 4, seg = idx & 15;
            size_t moff = (size_t)(kb * 32 + r) * 3072 + seg * 4;
            float4 k4 = *reinterpret_cast<const float4*>(kbase + moff);
            Ks[r][seg * 4 + 0] = k4.x; Ks[r][seg * 4 + 1] = k4.y;
            Ks[r][seg * 4 + 2] = k4.z; Ks[r][seg * 4 + 3] = k4.w;
            float4 v4 = *reinterpret_cast<const float4*>(vbase + moff);
            *reinterpret_cast<float4*>(&Vs[r][seg * 4]) = v4;
        }
        __syncthreads();

        // S = Q K^T, rows 4ty+a, cols 2tx+c
        float s[4][2] = {};
#pragma unroll
        for (int e0 = 0; e0 < 64; e0 += 2) {
            float2 q2[4], k2[2];
#pragma unroll
            for (int a = 0; a < 4; a++) q2[a] = *reinterpret_cast<const float2*>(&Qs[ty * 4 + a][e0]);
#pragma unroll
            for (int c = 0; c < 2; c++) k2[c] = *reinterpret_cast<const float2*>(&Ks[tx * 2 + c][e0]);
#pragma unroll
            for (int a = 0; a < 4; a++)
#pragma unroll
                for (int c = 0; c < 2; c++)
                    s[a][c] += q2[a].x * k2[c].x + q2[a].y * k2[c].y;
        }

        // online softmax (rows shared across 16-lane groups; shfl offsets <16 stay in-group)
#pragma unroll
        for (int a = 0; a < 4; a++) {
            float mx = fmaxf(s[a][0], s[a][1]);
#pragma unroll
            for (int off = 8; off; off >>= 1) mx = fmaxf(mx, __shfl_xor_sync(0xffffffffu, mx, off));
            float mnew = fmaxf(mrow[a], mx);
            float corr = __expf(mrow[a] - mnew);
            mrow[a] = mnew;
            float p0 = __expf(s[a][0] - mnew);
            float p1 = __expf(s[a][1] - mnew);
            float rs = p0 + p1;
#pragma unroll
            for (int off = 8; off; off >>= 1) rs += __shfl_xor_sync(0xffffffffu, rs, off);
            lrow[a] = lrow[a] * corr + rs;
#pragma unroll
            for (int c = 0; c < 4; c++) acc[a][c] *= corr;
            Ps[ty * 4 + a][tx * 2 + 0] = p0;
            Ps[ty * 4 + a][tx * 2 + 1] = p1;
        }
        __syncthreads();

        // O += P V, out dims 4tx+c
#pragma unroll
        for (int j0 = 0; j0 < 32; j0 += 4) {
            float4 p4[4], v4[4];
#pragma unroll
            for (int a = 0; a < 4; a++) p4[a] = *reinterpret_cast<const float4*>(&Ps[ty * 4 + a][j0]);
#pragma unroll
            for (int jj = 0; jj < 4; jj++) v4[jj] = *reinterpret_cast<const float4*>(&Vs[j0 + jj][tx * 4]);
#pragma unroll
            for (int a = 0; a < 4; a++) {
                acc[a][0] += p4[a].x * v4[0].x + p4[a].y * v4[1].x + p4[a].z * v4[2].x + p4[a].w * v4[3].x;
                acc[a][1] += p4[a].x * v4[0].y + p4[a].y * v4[1].y + p4[a].z * v4[2].y + p4[a].w * v4[3].y;
                acc[a][2] += p4[a].x * v4[0].z + p4[a].y * v4[1].z + p4[a].z * v4[2].z + p4[a].w * v4[3].z;
                acc[a][3] += p4[a].x * v4[0].w + p4[a].y * v4[1].w + p4[a].z * v4[2].w + p4[a].w * v4[3].w;
            }
        }
        __syncthreads();
    }

#pragma unroll
    for (int a = 0; a < 4; a++) {
        float invl = 1.0f / lrow[a];
        int m = b * L_SEQ + q0 + ty * 4 + a;
        float4 r;
        r.x = acc[a][0] * invl; r.y = acc[a][1] * invl;
        r.z = acc[a][2] * invl; r.w = acc[a][3] * invl;
        *reinterpret_cast<float4*>(o + (size_t)m * DMODEL + h * 64 + tx * 4) = r;
    }
}

// ---------------- SwiGLU: h = a * silu(g), u = [a | g] per row ----------------
__global__ void __launch_bounds__(256) swiglu_kernel(const float* __restrict__ u,
                                                     float* __restrict__ h)
{
    int idx = blockIdx.x * blockDim.x + threadIdx.x;  // over MTOT*DFF/4 exactly
    int m = idx / (DFF / 4);
    int j = idx % (DFF / 4);
    const float4* ur = reinterpret_cast<const float4*>(u) + (size_t)m * (2 * DFF / 4);
    float4 a = ur[j];
    float4 g = ur[DFF / 4 + j];
    float4 r;
    r.x = a.x * g.x / (1.f + expf(-g.x));
    r.y = a.y * g.y / (1.f + expf(-g.y));
    r.z = a.z * g.z / (1.f + expf(-g.z));
    r.w = a.w * g.w / (1.f + expf(-g.w));
    reinterpret_cast<float4*>(h)[idx] = r;
}

extern "C" void kernel_launch(void* const* d_in, const int* in_sizes, int n_in,
                              void* d_out, int out_size)
{
    const float* x          = (const float*)d_in[0];
    // d_in[1] = pos — unused by the reference
    const float* norm_scale = (const float*)d_in[2];
    const float* w_qkv      = (const float*)d_in[3];
    const float* attn_scale = (const float*)d_in[4];
    const float* w_out      = (const float*)d_in[5];
    const float* ff_scale   = (const float*)d_in[6];
    const float* w_up       = (const float*)d_in[7];
    const float* w_down     = (const float*)d_in[8];
    float* out = (float*)d_out;

    float *xn, *qkvp, *op, *up, *hp;
    cudaGetSymbolAddress((void**)&xn, g_xn);
    cudaGetSymbolAddress((void**)&qkvp, g_qkv);
    cudaGetSymbolAddress((void**)&op, g_o);
    cudaGetSymbolAddress((void**)&up, g_u);
    cudaGetSymbolAddress((void**)&hp, g_h);

    // 1) xn = rmsnorm(x)
    rmsnorm_kernel<<<MTOT, 256>>>(x, norm_scale, xn);
    // 2) qkv = xn @ w_qkv^T   [4096 x 3072]
    gemm_nt_kernel<<<dim3(3 * DMODEL / 128, MTOT / 128), 256>>>(xn, w_qkv, nullptr, qkvp, 3 * DMODEL, DMODEL);
    // 3) q,k cosine normalization with sqrt(attn_scale)
    qknorm_kernel<<<MTOT * 32 / 8, 256>>>(qkvp, attn_scale);
    // 4) attention -> o  [4096 x 1024]
    attention_kernel<<<dim3(L_SEQ / 64, NHEAD, BATCH), 256>>>(qkvp, op);
    // 5) x1 = o @ w_out^T + x   -> d_out
    gemm_nt_kernel<<<dim3(DMODEL / 128, MTOT / 128), 256>>>(op, w_out, x, out, DMODEL, DMODEL);
    // 6) xn = rmsnorm(x1)
    rmsnorm_kernel<<<MTOT, 256>>>(out, ff_scale, xn);
    // 7) u = xn @ w_up^T   [4096 x 6144]
    gemm_nt_kernel<<<dim3(2 * DFF / 128, MTOT / 128), 256>>>(xn, w_up, nullptr, up, 2 * DFF, DMODEL);
    // 8) h = a * silu(g)
    swiglu_kernel<<<MTOT * DFF / 4 / 256, 256>>>(up, hp);
    // 9) out = h @ w_down^T + x1 (in-place residual on d_out)
    gemm_nt_kernel<<<dim3(DMODEL / 128, MTOT / 128), 256>>>(hp, w_down, out, out, DMODEL, DFF);
}

// round 2
// speedup vs baseline: 1.4576x; 1.4576x over previous
#include <cuda_runtime.h>
#include <cstdint>

#define L_SEQ 2048
#define BATCH 2
#define DMODEL 1024
#define NHEAD 16
#define DHEAD 64
#define DFF 3072
#define MTOT (BATCH * L_SEQ) /* 4096 */

// -------- scratch (device globals: allocation-free rule) --------
__device__ float g_xn[MTOT * DMODEL];        // 16 MB
__device__ float g_qkv[MTOT * 3 * DMODEL];   // 48 MB
__device__ float g_o[MTOT * DMODEL];         // 16 MB
__device__ float g_u[MTOT * 2 * DFF];        // 96 MB
__device__ float g_h[MTOT * DFF];            // 48 MB

__device__ __forceinline__ unsigned f2tf32(float f) {
    unsigned r;
    asm("cvt.rna.tf32.f32 %0, %1;" : "=r"(r) : "f"(f));
    return r;
}

// ---------------- RMSNorm: one block per row, 256 thr x float4 ----------------
__global__ void __launch_bounds__(256) rmsnorm_kernel(const float* __restrict__ x,
                                                      const float* __restrict__ scale,
                                                      float* __restrict__ out)
{
    int row = blockIdx.x;
    int t = threadIdx.x;
    const float4* xr = reinterpret_cast<const float4*>(x) + (size_t)row * (DMODEL / 4);
    float4 v = xr[t];
    float ss = v.x * v.x + v.y * v.y + v.z * v.z + v.w * v.w;
#pragma unroll
    for (int o = 16; o; o >>= 1) ss += __shfl_xor_sync(0xffffffffu, ss, o);
    __shared__ float ws[8];
    if ((t & 31) == 0) ws[t >> 5] = ss;
    __syncthreads();
    float tot = 0.f;
#pragma unroll
    for (int i = 0; i < 8; i++) tot += ws[i];
    float inv = rsqrtf(tot * (1.0f / DMODEL) + 1e-6f);
    float4 s = reinterpret_cast<const float4*>(scale)[t];
    float4 r;
    r.x = v.x * s.x * inv;
    r.y = v.y * s.y * inv;
    r.z = v.z * s.z * inv;
    r.w = v.w * s.w * inv;
    (reinterpret_cast<float4*>(out) + (size_t)row * (DMODEL / 4))[t] = r;
}

// ---------------- TF32 tensor-core GEMM NT: C[m,n] = sum_k A[m,k]*B[n,k] (+resid) ----
// 128x128 block tile, BK=16, 256 threads = 8 warps (2x4), warp tile 64x32,
// mma.sync.m16n8k8 tf32. Smem holds tf32 bit patterns (converted once at store).
#define BKK 16
#define LDP 136  /* row pad: bank = 8*(k&3) + g -> conflict-free fragment loads */
__global__ void __launch_bounds__(256, 2) gemm_tf32_kernel(const float* __restrict__ A,
                                                           const float* __restrict__ B,
                                                           const float* resid,
                                                           float* __restrict__ C,
                                                           int N, int K)
{
    __shared__ unsigned As[BKK][LDP];
    __shared__ unsigned Bs[BKK][LDP];
    int tid = threadIdx.x;
    int warp = tid >> 5, lane = tid & 31;
    int g = lane >> 2, t = lane & 3;
    int m0 = blockIdx.y * 128, n0 = blockIdx.x * 128;
    int wm = (warp >> 2) * 64;   // warp m offset (0 or 64)
    int wn = (warp & 3) * 32;    // warp n offset (0..96)

    // global load mapping: lm = tid>>1 (row), lk = (tid&1)*8 (k offset); 2 float4 each
    int lm = tid >> 1;
    int lk = (tid & 1) * 8;
    const float* Ap = A + (size_t)(m0 + lm) * K + lk;
    const float* Bp = B + (size_t)(n0 + lm) * K + lk;

    float acc[4][4][4] = {};  // [mi][ni][c]

    float4 a0 = *reinterpret_cast<const float4*>(Ap);
    float4 a1 = *reinterpret_cast<const float4*>(Ap + 4);
    float4 b0 = *reinterpret_cast<const float4*>(Bp);
    float4 b1 = *reinterpret_cast<const float4*>(Bp + 4);

    for (int kt = 0; kt < K; kt += BKK) {
        As[lk + 0][lm] = f2tf32(a0.x); As[lk + 1][lm] = f2tf32(a0.y);
        As[lk + 2][lm] = f2tf32(a0.z); As[lk + 3][lm] = f2tf32(a0.w);
        As[lk + 4][lm] = f2tf32(a1.x); As[lk + 5][lm] = f2tf32(a1.y);
        As[lk + 6][lm] = f2tf32(a1.z); As[lk + 7][lm] = f2tf32(a1.w);
        Bs[lk + 0][lm] = f2tf32(b0.x); Bs[lk + 1][lm] = f2tf32(b0.y);
        Bs[lk + 2][lm] = f2tf32(b0.z); Bs[lk + 3][lm] = f2tf32(b0.w);
        Bs[lk + 4][lm] = f2tf32(b1.x); Bs[lk + 5][lm] = f2tf32(b1.y);
        Bs[lk + 6][lm] = f2tf32(b1.z); Bs[lk + 7][lm] = f2tf32(b1.w);
        __syncthreads();
        if (kt + BKK < K) {  // prefetch next tile
            a0 = *reinterpret_cast<const float4*>(Ap + kt + BKK);
            a1 = *reinterpret_cast<const float4*>(Ap + kt + BKK + 4);
            b0 = *reinterpret_cast<const float4*>(Bp + kt + BKK);
            b1 = *reinterpret_cast<const float4*>(Bp + kt + BKK + 4);
        }
#pragma unroll
        for (int ks = 0; ks < BKK; ks += 8) {
            unsigned af[4][4], bf[4][2];
#pragma unroll
            for (int mi = 0; mi < 4; mi++) {
                int mr = wm + mi * 16 + g;
                af[mi][0] = As[ks + t][mr];
                af[mi][1] = As[ks + t][mr + 8];
                af[mi][2] = As[ks + t + 4][mr];
                af[mi][3] = As[ks + t + 4][mr + 8];
            }
#pragma unroll
            for (int ni = 0; ni < 4; ni++) {
                int nc = wn + ni * 8 + g;
                bf[ni][0] = Bs[ks + t][nc];
                bf[ni][1] = Bs[ks + t + 4][nc];
            }
#pragma unroll
            for (int mi = 0; mi < 4; mi++)
#pragma unroll
                for (int ni = 0; ni < 4; ni++) {
                    asm volatile(
                        "mma.sync.aligned.m16n8k8.row.col.f32.tf32.tf32.f32 "
                        "{%0,%1,%2,%3}, {%4,%5,%6,%7}, {%8,%9}, {%0,%1,%2,%3};"
                        : "+f"(acc[mi][ni][0]), "+f"(acc[mi][ni][1]),
                          "+f"(acc[mi][ni][2]), "+f"(acc[mi][ni][3])
                        : "r"(af[mi][0]), "r"(af[mi][1]), "r"(af[mi][2]), "r"(af[mi][3]),
                          "r"(bf[ni][0]), "r"(bf[ni][1]));
                }
        }
        __syncthreads();
    }

    // epilogue: c0:(g, 2t) c1:(g, 2t+1) c2:(g+8, 2t) c3:(g+8, 2t+1)
#pragma unroll
    for (int mi = 0; mi < 4; mi++) {
#pragma unroll
        for (int ni = 0; ni < 4; ni++) {
            int row0 = m0 + wm + mi * 16 + g;
            int col = n0 + wn + ni * 8 + 2 * t;
            size_t i0 = (size_t)row0 * N + col;
            size_t i1 = (size_t)(row0 + 8) * N + col;
            float v0 = acc[mi][ni][0], v1 = acc[mi][ni][1];
            float v2 = acc[mi][ni][2], v3 = acc[mi][ni][3];
            if (resid) {
                v0 += resid[i0]; v1 += resid[i0 + 1];
                v2 += resid[i1]; v3 += resid[i1 + 1];
            }
            C[i0] = v0; C[i0 + 1] = v1;
            C[i1] = v2; C[i1 + 1] = v3;
        }
    }
}

// ---------------- QK cosine norm: one warp per (token, part, head) 64-vec ----------------
__global__ void __launch_bounds__(256) qknorm_kernel(float* __restrict__ qkv,
                                                     const float* __restrict__ attn_scale)
{
    int warp = blockIdx.x * (blockDim.x >> 5) + (threadIdx.x >> 5);
    int lane = threadIdx.x & 31;
    int m = warp >> 5;
    int rest = warp & 31;
    int part = rest >> 4;  // 0=q, 1=k
    int h = rest & 15;
    size_t base = (size_t)m * 3072 + part * 1024 + h * 64;
    float2 v = *reinterpret_cast<float2*>(qkv + base + lane * 2);
    float ss = v.x * v.x + v.y * v.y;
#pragma unroll
    for (int o = 16; o; o >>= 1) ss += __shfl_xor_sync(0xffffffffu, ss, o);
    float f = sqrtf(attn_scale[h]) * rsqrtf(ss + 1e-6f);
    v.x *= f;
    v.y *= f;
    *reinterpret_cast<float2*>(qkv + base + lane * 2) = v;
}

// ---------------- Flash attention: BM=64 queries, BN=32 keys per iter ----------------
__global__ void __launch_bounds__(256) attention_kernel(const float* __restrict__ qkv,
                                                        float* __restrict__ o)
{
    __shared__ float Qs[64][64];
    __shared__ float Ks[32][66];
    __shared__ float Vs[32][64];
    __shared__ float Ps[64][32];

    int tid = threadIdx.x;
    int tx = tid & 15, ty = tid >> 4;
    int q0 = blockIdx.x * 64;
    int h = blockIdx.y, b = blockIdx.z;
    const float* qbase = qkv + (size_t)b * L_SEQ * 3072 + h * 64;
    const float* kbase = qbase + 1024;
    const float* vbase = qbase + 2048;

#pragma unroll
    for (int j = 0; j < 4; j++) {
        int idx = tid + 256 * j;
        int r = idx >> 4, seg = idx & 15;
        float4 v = *reinterpret_cast<const float4*>(qbase + (size_t)(q0 + r) * 3072 + seg * 4);
        *reinterpret_cast<float4*>(&Qs[r][seg * 4]) = v;
    }

    float acc[4][4] = {};
    float mrow[4], lrow[4];
#pragma unroll
    for (int a = 0; a < 4; a++) { mrow[a] = -1e30f; lrow[a] = 0.f; }

    for (int kb = 0; kb < L_SEQ / 32; kb++) {
#pragma unroll
        for (int j = 0; j < 2; j++) {
            int idx = tid + 256 * j;
            int r = idx >> 4, seg = idx & 15;
            size_t moff = (size_t)(kb * 32 + r) * 3072 + seg * 4;
            float4 k4 = *reinterpret_cast<const float4*>(kbase + moff);
            Ks[r][seg * 4 + 0] = k4.x; Ks[r][seg * 4 + 1] = k4.y;
            Ks[r][seg * 4 + 2] = k4.z; Ks[r][seg * 4 + 3] = k4.w;
            float4 v4 = *reinterpret_cast<const float4*>(vbase + moff);
            *reinterpret_cast<float4*>(&Vs[r][seg * 4]) = v4;
        }
        __syncthreads();

        float s[4][2] = {};
#pragma unroll
        for (int e0 = 0; e0 < 64; e0 += 2) {
            float2 q2[4], k2[2];
#pragma unroll
            for (int a = 0; a < 4; a++) q2[a] = *reinterpret_cast<const float2*>(&Qs[ty * 4 + a][e0]);
#pragma unroll
            for (int c = 0; c < 2; c++) k2[c] = *reinterpret_cast<const float2*>(&Ks[tx * 2 + c][e0]);
#pragma unroll
            for (int a = 0; a < 4; a++)
#pragma unroll
                for (int c = 0; c < 2; c++)
                    s[a][c] += q2[a].x * k2[c].x + q2[a].y * k2[c].y;
        }

#pragma unroll
        for (int a = 0; a < 4; a++) {
            float mx = fmaxf(s[a][0], s[a][1]);
#pragma unroll
            for (int off = 8; off; off >>= 1) mx = fmaxf(mx, __shfl_xor_sync(0xffffffffu, mx, off));
            float mnew = fmaxf(mrow[a], mx);
            float corr = __expf(mrow[a] - mnew);
            mrow[a] = mnew;
            float p0 = __expf(s[a][0] - mnew);
            float p1 = __expf(s[a][1] - mnew);
            float rs = p0 + p1;
#pragma unroll
            for (int off = 8; off; off >>= 1) rs += __shfl_xor_sync(0xffffffffu, rs, off);
            lrow[a] = lrow[a] * corr + rs;
#pragma unroll
            for (int c = 0; c < 4; c++) acc[a][c] *= corr;
            Ps[ty * 4 + a][tx * 2 + 0] = p0;
            Ps[ty * 4 + a][tx * 2 + 1] = p1;
        }
        __syncthreads();

#pragma unroll
        for (int j0 = 0; j0 < 32; j0 += 4) {
            float4 p4[4], v4[4];
#pragma unroll
            for (int a = 0; a < 4; a++) p4[a] = *reinterpret_cast<const float4*>(&Ps[ty * 4 + a][j0]);
#pragma unroll
            for (int jj = 0; jj < 4; jj++) v4[jj] = *reinterpret_cast<const float4*>(&Vs[j0 + jj][tx * 4]);
#pragma unroll
            for (int a = 0; a < 4; a++) {
                acc[a][0] += p4[a].x * v4[0].x + p4[a].y * v4[1].x + p4[a].z * v4[2].x + p4[a].w * v4[3].x;
                acc[a][1] += p4[a].x * v4[0].y + p4[a].y * v4[1].y + p4[a].z * v4[2].y + p4[a].w * v4[3].y;
                acc[a][2] += p4[a].x * v4[0].z + p4[a].y * v4[1].z + p4[a].z * v4[2].z + p4[a].w * v4[3].z;
                acc[a][3] += p4[a].x * v4[0].w + p4[a].y * v4[1].w + p4[a].z * v4[2].w + p4[a].w * v4[3].w;
            }
        }
        __syncthreads();
    }

#pragma unroll
    for (int a = 0; a < 4; a++) {
        float invl = 1.0f / lrow[a];
        int m = b * L_SEQ + q0 + ty * 4 + a;
        float4 r;
        r.x = acc[a][0] * invl; r.y = acc[a][1] * invl;
        r.z = acc[a][2] * invl; r.w = acc[a][3] * invl;
        *reinterpret_cast<float4*>(o + (size_t)m * DMODEL + h * 64 + tx * 4) = r;
    }
}

// ---------------- SwiGLU: h = a * silu(g), u = [a | g] per row ----------------
__global__ void __launch_bounds__(256) swiglu_kernel(const float* __restrict__ u,
                                                     float* __restrict__ h)
{
    int idx = blockIdx.x * blockDim.x + threadIdx.x;
    int m = idx / (DFF / 4);
    int j = idx % (DFF / 4);
    const float4* ur = reinterpret_cast<const float4*>(u) + (size_t)m * (2 * DFF / 4);
    float4 a = ur[j];
    float4 g = ur[DFF / 4 + j];
    float4 r;
    r.x = a.x * g.x / (1.f + expf(-g.x));
    r.y = a.y * g.y / (1.f + expf(-g.y));
    r.z = a.z * g.z / (1.f + expf(-g.z));
    r.w = a.w * g.w / (1.f + expf(-g.w));
    reinterpret_cast<float4*>(h)[idx] = r;
}

extern "C" void kernel_launch(void* const* d_in, const int* in_sizes, int n_in,
                              void* d_out, int out_size)
{
    const float* x          = (const float*)d_in[0];
    const float* norm_scale = (const float*)d_in[2];
    const float* w_qkv      = (const float*)d_in[3];
    const float* attn_scale = (const float*)d_in[4];
    const float* w_out      = (const float*)d_in[5];
    const float* ff_scale   = (const float*)d_in[6];
    const float* w_up       = (const float*)d_in[7];
    const float* w_down     = (const float*)d_in[8];
    float* out = (float*)d_out;

    float *xn, *qkvp, *op, *up, *hp;
    cudaGetSymbolAddress((void**)&xn, g_xn);
    cudaGetSymbolAddress((void**)&qkvp, g_qkv);
    cudaGetSymbolAddress((void**)&op, g_o);
    cudaGetSymbolAddress((void**)&up, g_u);
    cudaGetSymbolAddress((void**)&hp, g_h);

    // 1) xn = rmsnorm(x)
    rmsnorm_kernel<<<MTOT, 256>>>(x, norm_scale, xn);
    // 2) qkv = xn @ w_qkv^T   [4096 x 3072]
    gemm_tf32_kernel<<<dim3(3 * DMODEL / 128, MTOT / 128), 256>>>(xn, w_qkv, nullptr, qkvp, 3 * DMODEL, DMODEL);
    // 3) q,k cosine normalization with sqrt(attn_scale)
    qknorm_kernel<<<MTOT * 32 / 8, 256>>>(qkvp, attn_scale);
    // 4) attention -> o  [4096 x 1024]
    attention_kernel<<<dim3(L_SEQ / 64, NHEAD, BATCH), 256>>>(qkvp, op);
    // 5) x1 = o @ w_out^T + x   -> d_out
    gemm_tf32_kernel<<<dim3(DMODEL / 128, MTOT / 128), 256>>>(op, w_out, x, out, DMODEL, DMODEL);
    // 6) xn = rmsnorm(x1)
    rmsnorm_kernel<<<MTOT, 256>>>(out, ff_scale, xn);
    // 7) u = xn @ w_up^T   [4096 x 6144]
    gemm_tf32_kernel<<<dim3(2 * DFF / 128, MTOT / 128), 256>>>(xn, w_up, nullptr, up, 2 * DFF, DMODEL);
    // 8) h = a * silu(g)
    swiglu_kernel<<<MTOT * DFF / 4 / 256, 256>>>(up, hp);
    // 9) out = h @ w_down^T + x1 (in-place residual on d_out)
    gemm_tf32_kernel<<<dim3(DMODEL / 128, MTOT / 128), 256>>>(hp, w_down, out, out, DMODEL, DFF);
}

// round 3
// speedup vs baseline: 1.8450x; 1.2658x over previous
#include <cuda_runtime.h>
#include <cstdint>

#define L_SEQ 2048
#define BATCH 2
#define DMODEL 1024
#define NHEAD 16
#define DHEAD 64
#define DFF 3072
#define MTOT (BATCH * L_SEQ) /* 4096 */

// -------- scratch (device globals: allocation-free rule) --------
__device__ float g_xn[MTOT * DMODEL];
__device__ float g_qkv[MTOT * 3 * DMODEL];
__device__ float g_o[MTOT * DMODEL];
__device__ float g_u[MTOT * 2 * DFF];
__device__ float g_h[MTOT * DFF];

__device__ __forceinline__ unsigned f2tf32(float f) {
    unsigned r;
    asm("cvt.rna.tf32.f32 %0, %1;" : "=r"(r) : "f"(f));
    return r;
}

// FFMA-only 2^y (no MUFU). Exact for integer part via magic-add; deg-5 poly on [-0.5,0.5].
__device__ __forceinline__ float fexp2(float y) {
    y = fmaxf(fminf(y, 120.f), -120.f);
    float z = y + 12582912.f;                 // 1.5*2^23
    int n = __float_as_int(z) - 0x4B400000;   // round(y)
    float f = y - (z - 12582912.f);           // y - n  in [-0.5, 0.5]
    float p = 0.0013333558f;
    p = fmaf(p, f, 0.0096181291f);
    p = fmaf(p, f, 0.0555041087f);
    p = fmaf(p, f, 0.2402265070f);
    p = fmaf(p, f, 0.6931471806f);
    p = fmaf(p, f, 1.0f);
    return __int_as_float((n + 127) << 23) * p;
}
#define L2E 1.4426950408889634f

// ---------------- RMSNorm ----------------
__global__ void __launch_bounds__(256) rmsnorm_kernel(const float* __restrict__ x,
                                                      const float* __restrict__ scale,
                                                      float* __restrict__ out)
{
    int row = blockIdx.x;
    int t = threadIdx.x;
    const float4* xr = reinterpret_cast<const float4*>(x) + (size_t)row * (DMODEL / 4);
    float4 v = xr[t];
    float ss = v.x * v.x + v.y * v.y + v.z * v.z + v.w * v.w;
#pragma unroll
    for (int o = 16; o; o >>= 1) ss += __shfl_xor_sync(0xffffffffu, ss, o);
    __shared__ float ws[8];
    if ((t & 31) == 0) ws[t >> 5] = ss;
    __syncthreads();
    float tot = 0.f;
#pragma unroll
    for (int i = 0; i < 8; i++) tot += ws[i];
    float inv = rsqrtf(tot * (1.0f / DMODEL) + 1e-6f);
    float4 s = reinterpret_cast<const float4*>(scale)[t];
    float4 r;
    r.x = v.x * s.x * inv;
    r.y = v.y * s.y * inv;
    r.z = v.z * s.z * inv;
    r.w = v.w * s.w * inv;
    (reinterpret_cast<float4*>(out) + (size_t)row * (DMODEL / 4))[t] = r;
}

// ---------------- TF32 tensor-core GEMM NT (unchanged from R1) ----------------
#define BKK 16
#define LDP 136
__global__ void __launch_bounds__(256, 2) gemm_tf32_kernel(const float* __restrict__ A,
                                                           const float* __restrict__ B,
                                                           const float* resid,
                                                           float* __restrict__ C,
                                                           int N, int K)
{
    __shared__ unsigned As[BKK][LDP];
    __shared__ unsigned Bs[BKK][LDP];
    int tid = threadIdx.x;
    int warp = tid >> 5, lane = tid & 31;
    int g = lane >> 2, t = lane & 3;
    int m0 = blockIdx.y * 128, n0 = blockIdx.x * 128;
    int wm = (warp >> 2) * 64;
    int wn = (warp & 3) * 32;

    int lm = tid >> 1;
    int lk = (tid & 1) * 8;
    const float* Ap = A + (size_t)(m0 + lm) * K + lk;
    const float* Bp = B + (size_t)(n0 + lm) * K + lk;

    float acc[4][4][4] = {};

    float4 a0 = *reinterpret_cast<const float4*>(Ap);
    float4 a1 = *reinterpret_cast<const float4*>(Ap + 4);
    float4 b0 = *reinterpret_cast<const float4*>(Bp);
    float4 b1 = *reinterpret_cast<const float4*>(Bp + 4);

    for (int kt = 0; kt < K; kt += BKK) {
        As[lk + 0][lm] = f2tf32(a0.x); As[lk + 1][lm] = f2tf32(a0.y);
        As[lk + 2][lm] = f2tf32(a0.z); As[lk + 3][lm] = f2tf32(a0.w);
        As[lk + 4][lm] = f2tf32(a1.x); As[lk + 5][lm] = f2tf32(a1.y);
        As[lk + 6][lm] = f2tf32(a1.z); As[lk + 7][lm] = f2tf32(a1.w);
        Bs[lk + 0][lm] = f2tf32(b0.x); Bs[lk + 1][lm] = f2tf32(b0.y);
        Bs[lk + 2][lm] = f2tf32(b0.z); Bs[lk + 3][lm] = f2tf32(b0.w);
        Bs[lk + 4][lm] = f2tf32(b1.x); Bs[lk + 5][lm] = f2tf32(b1.y);
        Bs[lk + 6][lm] = f2tf32(b1.z); Bs[lk + 7][lm] = f2tf32(b1.w);
        __syncthreads();
        if (kt + BKK < K) {
            a0 = *reinterpret_cast<const float4*>(Ap + kt + BKK);
            a1 = *reinterpret_cast<const float4*>(Ap + kt + BKK + 4);
            b0 = *reinterpret_cast<const float4*>(Bp + kt + BKK);
            b1 = *reinterpret_cast<const float4*>(Bp + kt + BKK + 4);
        }
#pragma unroll
        for (int ks = 0; ks < BKK; ks += 8) {
            unsigned af[4][4], bf[4][2];
#pragma unroll
            for (int mi = 0; mi < 4; mi++) {
                int mr = wm + mi * 16 + g;
                af[mi][0] = As[ks + t][mr];
                af[mi][1] = As[ks + t][mr + 8];
                af[mi][2] = As[ks + t + 4][mr];
                af[mi][3] = As[ks + t + 4][mr + 8];
            }
#pragma unroll
            for (int ni = 0; ni < 4; ni++) {
                int nc = wn + ni * 8 + g;
                bf[ni][0] = Bs[ks + t][nc];
                bf[ni][1] = Bs[ks + t + 4][nc];
            }
#pragma unroll
            for (int mi = 0; mi < 4; mi++)
#pragma unroll
                for (int ni = 0; ni < 4; ni++) {
                    asm volatile(
                        "mma.sync.aligned.m16n8k8.row.col.f32.tf32.tf32.f32 "
                        "{%0,%1,%2,%3}, {%4,%5,%6,%7}, {%8,%9}, {%0,%1,%2,%3};"
                        : "+f"(acc[mi][ni][0]), "+f"(acc[mi][ni][1]),
                          "+f"(acc[mi][ni][2]), "+f"(acc[mi][ni][3])
                        : "r"(af[mi][0]), "r"(af[mi][1]), "r"(af[mi][2]), "r"(af[mi][3]),
                          "r"(bf[ni][0]), "r"(bf[ni][1]));
                }
        }
        __syncthreads();
    }

#pragma unroll
    for (int mi = 0; mi < 4; mi++) {
#pragma unroll
        for (int ni = 0; ni < 4; ni++) {
            int row0 = m0 + wm + mi * 16 + g;
            int col = n0 + wn + ni * 8 + 2 * t;
            size_t i0 = (size_t)row0 * N + col;
            size_t i1 = (size_t)(row0 + 8) * N + col;
            float v0 = acc[mi][ni][0], v1 = acc[mi][ni][1];
            float v2 = acc[mi][ni][2], v3 = acc[mi][ni][3];
            if (resid) {
                v0 += resid[i0]; v1 += resid[i0 + 1];
                v2 += resid[i1]; v3 += resid[i1 + 1];
            }
            C[i0] = v0; C[i0 + 1] = v1;
            C[i1] = v2; C[i1 + 1] = v3;
        }
    }
}

// ---------------- QK cosine norm ----------------
__global__ void __launch_bounds__(256) qknorm_kernel(float* __restrict__ qkv,
                                                     const float* __restrict__ attn_scale)
{
    int warp = blockIdx.x * (blockDim.x >> 5) + (threadIdx.x >> 5);
    int lane = threadIdx.x & 31;
    int m = warp >> 5;
    int rest = warp & 31;
    int part = rest >> 4;
    int h = rest & 15;
    size_t base = (size_t)m * 3072 + part * 1024 + h * 64;
    float2 v = *reinterpret_cast<float2*>(qkv + base + lane * 2);
    float ss = v.x * v.x + v.y * v.y;
#pragma unroll
    for (int o = 16; o; o >>= 1) ss += __shfl_xor_sync(0xffffffffu, ss, o);
    float f = sqrtf(attn_scale[h]) * rsqrtf(ss + 1e-6f);
    v.x *= f;
    v.y *= f;
    *reinterpret_cast<float2*>(qkv + base + lane * 2) = v;
}

// ---------------- Tensor-core flash attention ----------------
// BM=64 queries, BN=32 keys/iter, 128 threads (4 warps, 16 rows each).
// QK^T: tf32 3-mma error compensation (~fp32 accurate logits).
// P*V: single tf32 (P in [0,1]); P via smem (warp-private region).
__global__ void __launch_bounds__(128) attention_tc_kernel(const float* __restrict__ qkv,
                                                           float* __restrict__ o)
{
    __shared__ float Qs[64][68];     // bank 4g+t: conflict-free
    __shared__ float Ks[32][68];
    __shared__ unsigned Vs[32][72];  // tf32 bits; bank 8t+g
    __shared__ unsigned Ps[64][36];  // tf32 bits; bank 4g+t

    int tid = threadIdx.x;
    int warp = tid >> 5, lane = tid & 31;
    int g = lane >> 2, t = lane & 3;
    int wm = warp * 16;
    int q0 = blockIdx.x * 64;
    int h = blockIdx.y, b = blockIdx.z;
    const float* qbase = qkv + (size_t)b * L_SEQ * 3072 + h * 64;
    const float* kbase = qbase + 1024;
    const float* vbase = qbase + 2048;

    // load Q tile 64x64
#pragma unroll
    for (int j = 0; j < 8; j++) {
        int idx = tid + 128 * j;
        int r = idx >> 4, seg = idx & 15;
        float4 v = *reinterpret_cast<const float4*>(qbase + (size_t)(q0 + r) * 3072 + seg * 4);
        *reinterpret_cast<float4*>(&Qs[r][seg * 4]) = v;
    }

    float oacc[8][4] = {};
    float mrow[2] = {-1e30f, -1e30f};
    float lrow[2] = {0.f, 0.f};

    for (int kb = 0; kb < L_SEQ / 32; kb++) {
        __syncthreads();  // prev iter's PV done before K/V overwrite (covers Q on iter 0)
#pragma unroll
        for (int j = 0; j < 4; j++) {
            int idx = tid + 128 * j;
            int r = idx >> 4, seg = idx & 15;
            size_t moff = (size_t)(kb * 32 + r) * 3072 + seg * 4;
            float4 k4 = *reinterpret_cast<const float4*>(kbase + moff);
            *reinterpret_cast<float4*>(&Ks[r][seg * 4]) = k4;
            float4 v4 = *reinterpret_cast<const float4*>(vbase + moff);
            uint4 u;
            u.x = f2tf32(v4.x); u.y = f2tf32(v4.y);
            u.z = f2tf32(v4.z); u.w = f2tf32(v4.w);
            *reinterpret_cast<uint4*>(&Vs[r][seg * 4]) = u;
        }
        __syncthreads();

        // ---- S = Q K^T (compensated tf32) ----
        float sacc[4][4] = {};
#pragma unroll
        for (int k0 = 0; k0 < 64; k0 += 8) {
            float qa[4];
            qa[0] = Qs[wm + g][k0 + t];
            qa[1] = Qs[wm + g + 8][k0 + t];
            qa[2] = Qs[wm + g][k0 + t + 4];
            qa[3] = Qs[wm + g + 8][k0 + t + 4];
            unsigned qbf[4], qsf[4];
#pragma unroll
            for (int i = 0; i < 4; i++) {
                qbf[i] = f2tf32(qa[i]);
                qsf[i] = f2tf32(qa[i] - __uint_as_float(qbf[i]));
            }
#pragma unroll
            for (int ni = 0; ni < 4; ni++) {
                float ka0 = Ks[ni * 8 + g][k0 + t];
                float ka1 = Ks[ni * 8 + g][k0 + t + 4];
                unsigned kb0 = f2tf32(ka0), kb1 = f2tf32(ka1);
                unsigned ks0 = f2tf32(ka0 - __uint_as_float(kb0));
                unsigned ks1 = f2tf32(ka1 - __uint_as_float(kb1));
#define MMA_S(A0,A1,A2,A3,B0,B1) \
                asm volatile("mma.sync.aligned.m16n8k8.row.col.f32.tf32.tf32.f32 " \
                    "{%0,%1,%2,%3}, {%4,%5,%6,%7}, {%8,%9}, {%0,%1,%2,%3};" \
                    : "+f"(sacc[ni][0]), "+f"(sacc[ni][1]), "+f"(sacc[ni][2]), "+f"(sacc[ni][3]) \
                    : "r"(A0), "r"(A1), "r"(A2), "r"(A3), "r"(B0), "r"(B1))
                MMA_S(qbf[0], qbf[1], qbf[2], qbf[3], kb0, kb1);
                MMA_S(qbf[0], qbf[1], qbf[2], qbf[3], ks0, ks1);
                MMA_S(qsf[0], qsf[1], qsf[2], qsf[3], kb0, kb1);
#undef MMA_S
            }
        }

        // ---- online softmax (rows g and g+8; quad = lanes with same g) ----
        float ml0 = -1e30f, ml1 = -1e30f;
#pragma unroll
        for (int ni = 0; ni < 4; ni++) {
            ml0 = fmaxf(ml0, fmaxf(sacc[ni][0], sacc[ni][1]));
            ml1 = fmaxf(ml1, fmaxf(sacc[ni][2], sacc[ni][3]));
        }
#pragma unroll
        for (int off = 1; off < 4; off <<= 1) {
            ml0 = fmaxf(ml0, __shfl_xor_sync(0xffffffffu, ml0, off));
            ml1 = fmaxf(ml1, __shfl_xor_sync(0xffffffffu, ml1, off));
        }
        float mn0 = fmaxf(mrow[0], ml0);
        float mn1 = fmaxf(mrow[1], ml1);
        float corr0 = fexp2((mrow[0] - mn0) * L2E);
        float corr1 = fexp2((mrow[1] - mn1) * L2E);
        mrow[0] = mn0; mrow[1] = mn1;

        float rs0 = 0.f, rs1 = 0.f;
#pragma unroll
        for (int ni = 0; ni < 4; ni++) {
            float p0 = fexp2((sacc[ni][0] - mn0) * L2E);
            float p1 = fexp2((sacc[ni][1] - mn0) * L2E);
            float p2 = fexp2((sacc[ni][2] - mn1) * L2E);
            float p3 = fexp2((sacc[ni][3] - mn1) * L2E);
            rs0 += p0 + p1;
            rs1 += p2 + p3;
            Ps[wm + g][ni * 8 + 2 * t] = f2tf32(p0);
            Ps[wm + g][ni * 8 + 2 * t + 1] = f2tf32(p1);
            Ps[wm + g + 8][ni * 8 + 2 * t] = f2tf32(p2);
            Ps[wm + g + 8][ni * 8 + 2 * t + 1] = f2tf32(p3);
        }
#pragma unroll
        for (int off = 1; off < 4; off <<= 1) {
            rs0 += __shfl_xor_sync(0xffffffffu, rs0, off);
            rs1 += __shfl_xor_sync(0xffffffffu, rs1, off);
        }
        lrow[0] = lrow[0] * corr0 + rs0;
        lrow[1] = lrow[1] * corr1 + rs1;
#pragma unroll
        for (int ni = 0; ni < 8; ni++) {
            oacc[ni][0] *= corr0; oacc[ni][1] *= corr0;
            oacc[ni][2] *= corr1; oacc[ni][3] *= corr1;
        }
        __syncwarp();  // Ps region is warp-private: warp sync suffices

        // ---- O += P V ----
#pragma unroll
        for (int k0 = 0; k0 < 32; k0 += 8) {
            unsigned pa0 = Ps[wm + g][k0 + t];
            unsigned pa1 = Ps[wm + g + 8][k0 + t];
            unsigned pa2 = Ps[wm + g][k0 + t + 4];
            unsigned pa3 = Ps[wm + g + 8][k0 + t + 4];
#pragma unroll
            for (int ni = 0; ni < 8; ni++) {
                unsigned vb0 = Vs[k0 + t][ni * 8 + g];
                unsigned vb1 = Vs[k0 + t + 4][ni * 8 + g];
                asm volatile("mma.sync.aligned.m16n8k8.row.col.f32.tf32.tf32.f32 "
                    "{%0,%1,%2,%3}, {%4,%5,%6,%7}, {%8,%9}, {%0,%1,%2,%3};"
                    : "+f"(oacc[ni][0]), "+f"(oacc[ni][1]), "+f"(oacc[ni][2]), "+f"(oacc[ni][3])
                    : "r"(pa0), "r"(pa1), "r"(pa2), "r"(pa3), "r"(vb0), "r"(vb1));
            }
        }
        __syncwarp();  // PV reads of Ps done before next iter's softmax rewrites
    }

    // epilogue
    float inv0 = 1.0f / lrow[0];
    float inv1 = 1.0f / lrow[1];
    int row0 = b * L_SEQ + q0 + wm + g;
    int row1 = row0 + 8;
#pragma unroll
    for (int ni = 0; ni < 8; ni++) {
        int col = h * 64 + ni * 8 + 2 * t;
        float2 r0 = make_float2(oacc[ni][0] * inv0, oacc[ni][1] * inv0);
        float2 r1 = make_float2(oacc[ni][2] * inv1, oacc[ni][3] * inv1);
        *reinterpret_cast<float2*>(o + (size_t)row0 * DMODEL + col) = r0;
        *reinterpret_cast<float2*>(o + (size_t)row1 * DMODEL + col) = r1;
    }
}

// ---------------- SwiGLU (FFMA exp, no MUFU) ----------------
__global__ void __launch_bounds__(256) swiglu_kernel(const float* __restrict__ u,
                                                     float* __restrict__ h)
{
    int idx = blockIdx.x * blockDim.x + threadIdx.x;
    int m = idx / (DFF / 4);
    int j = idx % (DFF / 4);
    const float4* ur = reinterpret_cast<const float4*>(u) + (size_t)m * (2 * DFF / 4);
    float4 a = ur[j];
    float4 g = ur[DFF / 4 + j];
    float4 r;
    r.x = a.x * g.x / (1.f + fexp2(-g.x * L2E));
    r.y = a.y * g.y / (1.f + fexp2(-g.y * L2E));
    r.z = a.z * g.z / (1.f + fexp2(-g.z * L2E));
    r.w = a.w * g.w / (1.f + fexp2(-g.w * L2E));
    reinterpret_cast<float4*>(h)[idx] = r;
}

extern "C" void kernel_launch(void* const* d_in, const int* in_sizes, int n_in,
                              void* d_out, int out_size)
{
    const float* x          = (const float*)d_in[0];
    const float* norm_scale = (const float*)d_in[2];
    const float* w_qkv      = (const float*)d_in[3];
    const float* attn_scale = (const float*)d_in[4];
    const float* w_out      = (const float*)d_in[5];
    const float* ff_scale   = (const float*)d_in[6];
    const float* w_up       = (const float*)d_in[7];
    const float* w_down     = (const float*)d_in[8];
    float* out = (float*)d_out;

    float *xn, *qkvp, *op, *up, *hp;
    cudaGetSymbolAddress((void**)&xn, g_xn);
    cudaGetSymbolAddress((void**)&qkvp, g_qkv);
    cudaGetSymbolAddress((void**)&op, g_o);
    cudaGetSymbolAddress((void**)&up, g_u);
    cudaGetSymbolAddress((void**)&hp, g_h);

    rmsnorm_kernel<<<MTOT, 256>>>(x, norm_scale, xn);
    gemm_tf32_kernel<<<dim3(3 * DMODEL / 128, MTOT / 128), 256>>>(xn, w_qkv, nullptr, qkvp, 3 * DMODEL, DMODEL);
    qknorm_kernel<<<MTOT * 32 / 8, 256>>>(qkvp, attn_scale);
    attention_tc_kernel<<<dim3(L_SEQ / 64, NHEAD, BATCH), 128>>>(qkvp, op);
    gemm_tf32_kernel<<<dim3(DMODEL / 128, MTOT / 128), 256>>>(op, w_out, x, out, DMODEL, DMODEL);
    rmsnorm_kernel<<<MTOT, 256>>>(out, ff_scale, xn);
    gemm_tf32_kernel<<<dim3(2 * DFF / 128, MTOT / 128), 256>>>(xn, w_up, nullptr, up, 2 * DFF, DMODEL);
    swiglu_kernel<<<MTOT * DFF / 4 / 256, 256>>>(up, hp);
    gemm_tf32_kernel<<<dim3(DMODEL / 128, MTOT / 128), 256>>>(hp, w_down, out, out, DMODEL, DFF);
}

// round 4
// speedup vs baseline: 1.9643x; 1.0647x over previous
#include <cuda_runtime.h>
#include <cstdint>

#define L_SEQ 2048
#define BATCH 2
#define DMODEL 1024
#define NHEAD 16
#define DHEAD 64
#define DFF 3072
#define MTOT (BATCH * L_SEQ) /* 4096 */

// -------- scratch (device globals: allocation-free rule) --------
__device__ float g_xn[MTOT * DMODEL];
__device__ float g_qkv[MTOT * 3 * DMODEL];
__device__ float g_o[MTOT * DMODEL];
__device__ float g_u[MTOT * 2 * DFF];
__device__ float g_h[MTOT * DFF];

__device__ __forceinline__ unsigned f2tf32(float f) {
    unsigned r;
    asm("cvt.rna.tf32.f32 %0, %1;" : "=r"(r) : "f"(f));
    return r;
}

// FFMA-only 2^y (no MUFU).
__device__ __forceinline__ float fexp2(float y) {
    y = fmaxf(fminf(y, 120.f), -120.f);
    float z = y + 12582912.f;                 // 1.5*2^23
    int n = __float_as_int(z) - 0x4B400000;   // round(y)
    float f = y - (z - 12582912.f);           // y - n in [-0.5, 0.5]
    float p = 0.0013333558f;
    p = fmaf(p, f, 0.0096181291f);
    p = fmaf(p, f, 0.0555041087f);
    p = fmaf(p, f, 0.2402265070f);
    p = fmaf(p, f, 0.6931471806f);
    p = fmaf(p, f, 1.0f);
    return __int_as_float((n + 127) << 23) * p;
}
#define L2E 1.4426950408889634f

// ---------------- RMSNorm ----------------
__global__ void __launch_bounds__(256) rmsnorm_kernel(const float* __restrict__ x,
                                                      const float* __restrict__ scale,
                                                      float* __restrict__ out)
{
    int row = blockIdx.x;
    int t = threadIdx.x;
    const float4* xr = reinterpret_cast<const float4*>(x) + (size_t)row * (DMODEL / 4);
    float4 v = xr[t];
    float ss = v.x * v.x + v.y * v.y + v.z * v.z + v.w * v.w;
#pragma unroll
    for (int o = 16; o; o >>= 1) ss += __shfl_xor_sync(0xffffffffu, ss, o);
    __shared__ float ws[8];
    if ((t & 31) == 0) ws[t >> 5] = ss;
    __syncthreads();
    float tot = 0.f;
#pragma unroll
    for (int i = 0; i < 8; i++) tot += ws[i];
    float inv = rsqrtf(tot * (1.0f / DMODEL) + 1e-6f);
    float4 s = reinterpret_cast<const float4*>(scale)[t];
    float4 r;
    r.x = v.x * s.x * inv;
    r.y = v.y * s.y * inv;
    r.z = v.z * s.z * inv;
    r.w = v.w * s.w * inv;
    (reinterpret_cast<float4*>(out) + (size_t)row * (DMODEL / 4))[t] = r;
}

// ---------------- TF32 tensor-core GEMM NT ----------------
#define BKK 16
#define LDP 136
__global__ void __launch_bounds__(256, 2) gemm_tf32_kernel(const float* __restrict__ A,
                                                           const float* __restrict__ B,
                                                           const float* resid,
                                                           float* __restrict__ C,
                                                           int N, int K)
{
    __shared__ unsigned As[BKK][LDP];
    __shared__ unsigned Bs[BKK][LDP];
    int tid = threadIdx.x;
    int warp = tid >> 5, lane = tid & 31;
    int g = lane >> 2, t = lane & 3;
    int m0 = blockIdx.y * 128, n0 = blockIdx.x * 128;
    int wm = (warp >> 2) * 64;
    int wn = (warp & 3) * 32;

    int lm = tid >> 1;
    int lk = (tid & 1) * 8;
    const float* Ap = A + (size_t)(m0 + lm) * K + lk;
    const float* Bp = B + (size_t)(n0 + lm) * K + lk;

    float acc[4][4][4] = {};

    float4 a0 = *reinterpret_cast<const float4*>(Ap);
    float4 a1 = *reinterpret_cast<const float4*>(Ap + 4);
    float4 b0 = *reinterpret_cast<const float4*>(Bp);
    float4 b1 = *reinterpret_cast<const float4*>(Bp + 4);

    for (int kt = 0; kt < K; kt += BKK) {
        As[lk + 0][lm] = f2tf32(a0.x); As[lk + 1][lm] = f2tf32(a0.y);
        As[lk + 2][lm] = f2tf32(a0.z); As[lk + 3][lm] = f2tf32(a0.w);
        As[lk + 4][lm] = f2tf32(a1.x); As[lk + 5][lm] = f2tf32(a1.y);
        As[lk + 6][lm] = f2tf32(a1.z); As[lk + 7][lm] = f2tf32(a1.w);
        Bs[lk + 0][lm] = f2tf32(b0.x); Bs[lk + 1][lm] = f2tf32(b0.y);
        Bs[lk + 2][lm] = f2tf32(b0.z); Bs[lk + 3][lm] = f2tf32(b0.w);
        Bs[lk + 4][lm] = f2tf32(b1.x); Bs[lk + 5][lm] = f2tf32(b1.y);
        Bs[lk + 6][lm] = f2tf32(b1.z); Bs[lk + 7][lm] = f2tf32(b1.w);
        __syncthreads();
        if (kt + BKK < K) {
            a0 = *reinterpret_cast<const float4*>(Ap + kt + BKK);
            a1 = *reinterpret_cast<const float4*>(Ap + kt + BKK + 4);
            b0 = *reinterpret_cast<const float4*>(Bp + kt + BKK);
            b1 = *reinterpret_cast<const float4*>(Bp + kt + BKK + 4);
        }
#pragma unroll
        for (int ks = 0; ks < BKK; ks += 8) {
            unsigned af[4][4], bf[4][2];
#pragma unroll
            for (int mi = 0; mi < 4; mi++) {
                int mr = wm + mi * 16 + g;
                af[mi][0] = As[ks + t][mr];
                af[mi][1] = As[ks + t][mr + 8];
                af[mi][2] = As[ks + t + 4][mr];
                af[mi][3] = As[ks + t + 4][mr + 8];
            }
#pragma unroll
            for (int ni = 0; ni < 4; ni++) {
                int nc = wn + ni * 8 + g;
                bf[ni][0] = Bs[ks + t][nc];
                bf[ni][1] = Bs[ks + t + 4][nc];
            }
#pragma unroll
            for (int mi = 0; mi < 4; mi++)
#pragma unroll
                for (int ni = 0; ni < 4; ni++) {
                    asm volatile(
                        "mma.sync.aligned.m16n8k8.row.col.f32.tf32.tf32.f32 "
                        "{%0,%1,%2,%3}, {%4,%5,%6,%7}, {%8,%9}, {%0,%1,%2,%3};"
                        : "+f"(acc[mi][ni][0]), "+f"(acc[mi][ni][1]),
                          "+f"(acc[mi][ni][2]), "+f"(acc[mi][ni][3])
                        : "r"(af[mi][0]), "r"(af[mi][1]), "r"(af[mi][2]), "r"(af[mi][3]),
                          "r"(bf[ni][0]), "r"(bf[ni][1]));
                }
        }
        __syncthreads();
    }

#pragma unroll
    for (int mi = 0; mi < 4; mi++) {
#pragma unroll
        for (int ni = 0; ni < 4; ni++) {
            int row0 = m0 + wm + mi * 16 + g;
            int col = n0 + wn + ni * 8 + 2 * t;
            size_t i0 = (size_t)row0 * N + col;
            size_t i1 = (size_t)(row0 + 8) * N + col;
            float2 v01 = make_float2(acc[mi][ni][0], acc[mi][ni][1]);
            float2 v23 = make_float2(acc[mi][ni][2], acc[mi][ni][3]);
            if (resid) {
                float2 r0 = *reinterpret_cast<const float2*>(resid + i0);
                float2 r1 = *reinterpret_cast<const float2*>(resid + i1);
                v01.x += r0.x; v01.y += r0.y;
                v23.x += r1.x; v23.y += r1.y;
            }
            *reinterpret_cast<float2*>(C + i0) = v01;
            *reinterpret_cast<float2*>(C + i1) = v23;
        }
    }
}

// ---------------- QK cosine norm ----------------
__global__ void __launch_bounds__(256) qknorm_kernel(float* __restrict__ qkv,
                                                     const float* __restrict__ attn_scale)
{
    int warp = blockIdx.x * (blockDim.x >> 5) + (threadIdx.x >> 5);
    int lane = threadIdx.x & 31;
    int m = warp >> 5;
    int rest = warp & 31;
    int part = rest >> 4;
    int h = rest & 15;
    size_t base = (size_t)m * 3072 + part * 1024 + h * 64;
    float2 v = *reinterpret_cast<float2*>(qkv + base + lane * 2);
    float ss = v.x * v.x + v.y * v.y;
#pragma unroll
    for (int o = 16; o; o >>= 1) ss += __shfl_xor_sync(0xffffffffu, ss, o);
    float f = sqrtf(attn_scale[h]) * rsqrtf(ss + 1e-6f);
    v.x *= f;
    v.y *= f;
    *reinterpret_cast<float2*>(qkv + base + lane * 2) = v;
}

// ---------------- Tensor-core flash attention v2 ----------------
// BM=64, BN=32, 128 threads. Q fragments hoisted to registers (split once);
// K pre-split big/small tf32 at tile load (smem reuses Q staging buffer).
__global__ void __launch_bounds__(128) attention_tc_kernel(const float* __restrict__ qkv,
                                                           float* __restrict__ o)
{
    // union region: Q staging (64x68 f32) then K big/small (2 x 32x68 u32)
    __shared__ __align__(16) char qk_raw[64 * 68 * 4];
    float (*Qs)[68] = reinterpret_cast<float(*)[68]>(qk_raw);
    unsigned (*KsB)[68] = reinterpret_cast<unsigned(*)[68]>(qk_raw);
    unsigned (*KsS)[68] = reinterpret_cast<unsigned(*)[68]>(qk_raw + 32 * 68 * 4);
    __shared__ unsigned Vs[32][72];
    __shared__ unsigned Ps[64][36];

    int tid = threadIdx.x;
    int warp = tid >> 5, lane = tid & 31;
    int g = lane >> 2, t = lane & 3;
    int wm = warp * 16;
    int q0 = blockIdx.x * 64;
    int h = blockIdx.y, b = blockIdx.z;
    const float* qbase = qkv + (size_t)b * L_SEQ * 3072 + h * 64;
    const float* kbase = qbase + 1024;
    const float* vbase = qbase + 2048;

    // stage Q tile 64x64 into smem
#pragma unroll
    for (int j = 0; j < 8; j++) {
        int idx = tid + 128 * j;
        int r = idx >> 4, seg = idx & 15;
        float4 v = *reinterpret_cast<const float4*>(qbase + (size_t)(q0 + r) * 3072 + seg * 4);
        *reinterpret_cast<float4*>(&Qs[r][seg * 4]) = v;
    }
    __syncthreads();

    // extract Q fragments once: qb/qs [8 k0-steps][4 regs]
    unsigned qb[32], qs[32];
#pragma unroll
    for (int k0 = 0; k0 < 8; k0++) {
        float qa[4];
        qa[0] = Qs[wm + g][k0 * 8 + t];
        qa[1] = Qs[wm + g + 8][k0 * 8 + t];
        qa[2] = Qs[wm + g][k0 * 8 + t + 4];
        qa[3] = Qs[wm + g + 8][k0 * 8 + t + 4];
#pragma unroll
        for (int i = 0; i < 4; i++) {
            unsigned big = f2tf32(qa[i]);
            qb[k0 * 4 + i] = big;
            qs[k0 * 4 + i] = f2tf32(qa[i] - __uint_as_float(big));
        }
    }

    float oacc[8][4] = {};
    float mrow[2] = {-1e30f, -1e30f};
    float lrow[2] = {0.f, 0.f};

    for (int kb = 0; kb < L_SEQ / 32; kb++) {
        __syncthreads();  // prev PV done; also guards Q-frag extraction on iter 0
#pragma unroll
        for (int j = 0; j < 4; j++) {
            int idx = tid + 128 * j;
            int r = idx >> 4, seg = idx & 15;
            size_t moff = (size_t)(kb * 32 + r) * 3072 + seg * 4;
            float4 k4 = *reinterpret_cast<const float4*>(kbase + moff);
            unsigned b0 = f2tf32(k4.x), b1 = f2tf32(k4.y);
            unsigned b2 = f2tf32(k4.z), b3 = f2tf32(k4.w);
            KsB[r][seg * 4 + 0] = b0; KsB[r][seg * 4 + 1] = b1;
            KsB[r][seg * 4 + 2] = b2; KsB[r][seg * 4 + 3] = b3;
            KsS[r][seg * 4 + 0] = f2tf32(k4.x - __uint_as_float(b0));
            KsS[r][seg * 4 + 1] = f2tf32(k4.y - __uint_as_float(b1));
            KsS[r][seg * 4 + 2] = f2tf32(k4.z - __uint_as_float(b2));
            KsS[r][seg * 4 + 3] = f2tf32(k4.w - __uint_as_float(b3));
            float4 v4 = *reinterpret_cast<const float4*>(vbase + moff);
            uint4 u;
            u.x = f2tf32(v4.x); u.y = f2tf32(v4.y);
            u.z = f2tf32(v4.z); u.w = f2tf32(v4.w);
            *reinterpret_cast<uint4*>(&Vs[r][seg * 4]) = u;
        }
        __syncthreads();

        // ---- S = Q K^T (compensated tf32, Q from registers) ----
        float sacc[4][4] = {};
#pragma unroll
        for (int k0 = 0; k0 < 8; k0++) {
            const unsigned* qbp = qb + k0 * 4;
            const unsigned* qsp = qs + k0 * 4;
#pragma unroll
            for (int ni = 0; ni < 4; ni++) {
                unsigned kb0 = KsB[ni * 8 + g][k0 * 8 + t];
                unsigned kb1 = KsB[ni * 8 + g][k0 * 8 + t + 4];
                unsigned ks0 = KsS[ni * 8 + g][k0 * 8 + t];
                unsigned ks1 = KsS[ni * 8 + g][k0 * 8 + t + 4];
#define MMA_S(A0,A1,A2,A3,B0,B1) \
                asm volatile("mma.sync.aligned.m16n8k8.row.col.f32.tf32.tf32.f32 " \
                    "{%0,%1,%2,%3}, {%4,%5,%6,%7}, {%8,%9}, {%0,%1,%2,%3};" \
                    : "+f"(sacc[ni][0]), "+f"(sacc[ni][1]), "+f"(sacc[ni][2]), "+f"(sacc[ni][3]) \
                    : "r"(A0), "r"(A1), "r"(A2), "r"(A3), "r"(B0), "r"(B1))
                MMA_S(qbp[0], qbp[1], qbp[2], qbp[3], kb0, kb1);
                MMA_S(qbp[0], qbp[1], qbp[2], qbp[3], ks0, ks1);
                MMA_S(qsp[0], qsp[1], qsp[2], qsp[3], kb0, kb1);
#undef MMA_S
            }
        }

        // ---- online softmax ----
        float ml0 = -1e30f, ml1 = -1e30f;
#pragma unroll
        for (int ni = 0; ni < 4; ni++) {
            ml0 = fmaxf(ml0, fmaxf(sacc[ni][0], sacc[ni][1]));
            ml1 = fmaxf(ml1, fmaxf(sacc[ni][2], sacc[ni][3]));
        }
#pragma unroll
        for (int off = 1; off < 4; off <<= 1) {
            ml0 = fmaxf(ml0, __shfl_xor_sync(0xffffffffu, ml0, off));
            ml1 = fmaxf(ml1, __shfl_xor_sync(0xffffffffu, ml1, off));
        }
        float mn0 = fmaxf(mrow[0], ml0);
        float mn1 = fmaxf(mrow[1], ml1);
        float corr0 = fexp2((mrow[0] - mn0) * L2E);
        float corr1 = fexp2((mrow[1] - mn1) * L2E);
        mrow[0] = mn0; mrow[1] = mn1;

        float rs0 = 0.f, rs1 = 0.f;
#pragma unroll
        for (int ni = 0; ni < 4; ni++) {
            float p0 = fexp2((sacc[ni][0] - mn0) * L2E);
            float p1 = fexp2((sacc[ni][1] - mn0) * L2E);
            float p2 = fexp2((sacc[ni][2] - mn1) * L2E);
            float p3 = fexp2((sacc[ni][3] - mn1) * L2E);
            rs0 += p0 + p1;
            rs1 += p2 + p3;
            Ps[wm + g][ni * 8 + 2 * t] = f2tf32(p0);
            Ps[wm + g][ni * 8 + 2 * t + 1] = f2tf32(p1);
            Ps[wm + g + 8][ni * 8 + 2 * t] = f2tf32(p2);
            Ps[wm + g + 8][ni * 8 + 2 * t + 1] = f2tf32(p3);
        }
#pragma unroll
        for (int off = 1; off < 4; off <<= 1) {
            rs0 += __shfl_xor_sync(0xffffffffu, rs0, off);
            rs1 += __shfl_xor_sync(0xffffffffu, rs1, off);
        }
        lrow[0] = lrow[0] * corr0 + rs0;
        lrow[1] = lrow[1] * corr1 + rs1;
#pragma unroll
        for (int ni = 0; ni < 8; ni++) {
            oacc[ni][0] *= corr0; oacc[ni][1] *= corr0;
            oacc[ni][2] *= corr1; oacc[ni][3] *= corr1;
        }
        __syncwarp();  // Ps warp-private

        // ---- O += P V ----
#pragma unroll
        for (int k0 = 0; k0 < 32; k0 += 8) {
            unsigned pa0 = Ps[wm + g][k0 + t];
            unsigned pa1 = Ps[wm + g + 8][k0 + t];
            unsigned pa2 = Ps[wm + g][k0 + t + 4];
            unsigned pa3 = Ps[wm + g + 8][k0 + t + 4];
#pragma unroll
            for (int ni = 0; ni < 8; ni++) {
                unsigned vb0 = Vs[k0 + t][ni * 8 + g];
                unsigned vb1 = Vs[k0 + t + 4][ni * 8 + g];
                asm volatile("mma.sync.aligned.m16n8k8.row.col.f32.tf32.tf32.f32 "
                    "{%0,%1,%2,%3}, {%4,%5,%6,%7}, {%8,%9}, {%0,%1,%2,%3};"
                    : "+f"(oacc[ni][0]), "+f"(oacc[ni][1]), "+f"(oacc[ni][2]), "+f"(oacc[ni][3])
                    : "r"(pa0), "r"(pa1), "r"(pa2), "r"(pa3), "r"(vb0), "r"(vb1));
            }
        }
        __syncwarp();
    }

    float inv0 = 1.0f / lrow[0];
    float inv1 = 1.0f / lrow[1];
    int row0 = b * L_SEQ + q0 + wm + g;
    int row1 = row0 + 8;
#pragma unroll
    for (int ni = 0; ni < 8; ni++) {
        int col = h * 64 + ni * 8 + 2 * t;
        float2 r0 = make_float2(oacc[ni][0] * inv0, oacc[ni][1] * inv0);
        float2 r1 = make_float2(oacc[ni][2] * inv1, oacc[ni][3] * inv1);
        *reinterpret_cast<float2*>(o + (size_t)row0 * DMODEL + col) = r0;
        *reinterpret_cast<float2*>(o + (size_t)row1 * DMODEL + col) = r1;
    }
}

// ---------------- SwiGLU ----------------
__global__ void __launch_bounds__(256) swiglu_kernel(const float* __restrict__ u,
                                                     float* __restrict__ h)
{
    int idx = blockIdx.x * blockDim.x + threadIdx.x;
    int m = idx / (DFF / 4);
    int j = idx % (DFF / 4);
    const float4* ur = reinterpret_cast<const float4*>(u) + (size_t)m * (2 * DFF / 4);
    float4 a = ur[j];
    float4 g = ur[DFF / 4 + j];
    float4 r;
    r.x = a.x * g.x / (1.f + fexp2(-g.x * L2E));
    r.y = a.y * g.y / (1.f + fexp2(-g.y * L2E));
    r.z = a.z * g.z / (1.f + fexp2(-g.z * L2E));
    r.w = a.w * g.w / (1.f + fexp2(-g.w * L2E));
    reinterpret_cast<float4*>(h)[idx] = r;
}

extern "C" void kernel_launch(void* const* d_in, const int* in_sizes, int n_in,
                              void* d_out, int out_size)
{
    const float* x          = (const float*)d_in[0];
    const float* norm_scale = (const float*)d_in[2];
    const float* w_qkv      = (const float*)d_in[3];
    const float* attn_scale = (const float*)d_in[4];
    const float* w_out      = (const float*)d_in[5];
    const float* ff_scale   = (const float*)d_in[6];
    const float* w_up       = (const float*)d_in[7];
    const float* w_down     = (const float*)d_in[8];
    float* out = (float*)d_out;

    float *xn, *qkvp, *op, *up, *hp;
    cudaGetSymbolAddress((void**)&xn, g_xn);
    cudaGetSymbolAddress((void**)&qkvp, g_qkv);
    cudaGetSymbolAddress((void**)&op, g_o);
    cudaGetSymbolAddress((void**)&up, g_u);
    cudaGetSymbolAddress((void**)&hp, g_h);

    rmsnorm_kernel<<<MTOT, 256>>>(x, norm_scale, xn);
    gemm_tf32_kernel<<<dim3(3 * DMODEL / 128, MTOT / 128), 256>>>(xn, w_qkv, nullptr, qkvp, 3 * DMODEL, DMODEL);
    qknorm_kernel<<<MTOT * 32 / 8, 256>>>(qkvp, attn_scale);
    attention_tc_kernel<<<dim3(L_SEQ / 64, NHEAD, BATCH), 128>>>(qkvp, op);
    gemm_tf32_kernel<<<dim3(DMODEL / 128, MTOT / 128), 256>>>(op, w_out, x, out, DMODEL, DMODEL);
    rmsnorm_kernel<<<MTOT, 256>>>(out, ff_scale, xn);
    gemm_tf32_kernel<<<dim3(2 * DFF / 128, MTOT / 128), 256>>>(xn, w_up, nullptr, up, 2 * DFF, DMODEL);
    swiglu_kernel<<<MTOT * DFF / 4 / 256, 256>>>(up, hp);
    gemm_tf32_kernel<<<dim3(DMODEL / 128, MTOT / 128), 256>>>(hp, w_down, out, out, DMODEL, DFF);
}